// round 1
// baseline (speedup 1.0000x reference)
#include <cuda_runtime.h>
#include <math.h>

// Problem constants
#define BB 4
#define SS 2048
#define DD 512
#define HH 8
#define DKK 64
#define FFF 2048
#define MM (BB * SS)   // 8192 rows

// ---------------------------------------------------------------------------
// Scratch (device globals — no allocation allowed)
// ---------------------------------------------------------------------------
__device__ float g_q  [MM * DD];   // q proj, later reused as pre-LN buffer
__device__ float g_k  [MM * DD];
__device__ float g_v  [MM * DD];
__device__ float g_ctx[MM * DD];
__device__ float g_h  [MM * DD];   // post-LN1
__device__ float g_ffn[MM * FFF];  // FFN hidden

// ---------------------------------------------------------------------------
// SGEMM: C[M,N] = A[M,K] @ B[K,N] + bias (+ residual) (optional ReLU)
// 128x128 block tile, BK=8, 256 threads, 8x8 per-thread microtile.
// All dims here are multiples of 128 (M=8192; N=512/2048; K=512/2048) -> no guards.
// ---------------------------------------------------------------------------
__global__ __launch_bounds__(256) void sgemm_kernel(
    const float* __restrict__ A, const float* __restrict__ Bw,
    const float* __restrict__ bias, const float* __restrict__ resid,
    float* __restrict__ C, int M, int N, int K, int relu)
{
    const int bx = blockIdx.x, by = blockIdx.y;
    const int tid = threadIdx.x;
    const int tx = tid & 15;       // 0..15  (col group)
    const int ty = tid >> 4;       // 0..15  (row group)

    __shared__ float As[8][128];   // transposed A tile: As[k][m]
    __shared__ float Bs[8][128];   // Bs[k][n]

    const int row0 = by * 128;
    const int col0 = bx * 128;

    const int aRow = tid >> 1;          // 0..127
    const int aCol = (tid & 1) * 4;     // 0 or 4
    const int bRow = tid >> 5;          // 0..7
    const int bCol = (tid & 31) * 4;    // 0..124

    const float* Aptr = A + (size_t)(row0 + aRow) * K + aCol;
    const float* Bptr = Bw + (size_t)bRow * N + col0 + bCol;

    float acc[8][8];
#pragma unroll
    for (int i = 0; i < 8; i++)
#pragma unroll
        for (int j = 0; j < 8; j++) acc[i][j] = 0.f;

    for (int k0 = 0; k0 < K; k0 += 8) {
        float4 a4 = *(const float4*)(Aptr + k0);
        float4 b4 = *(const float4*)(Bptr + (size_t)k0 * N);
        __syncthreads();
        As[aCol + 0][aRow] = a4.x;
        As[aCol + 1][aRow] = a4.y;
        As[aCol + 2][aRow] = a4.z;
        As[aCol + 3][aRow] = a4.w;
        *(float4*)&Bs[bRow][bCol] = b4;
        __syncthreads();

#pragma unroll
        for (int kk = 0; kk < 8; kk++) {
            float ar[8], br[8];
            *(float4*)&ar[0] = *(const float4*)&As[kk][ty * 8];
            *(float4*)&ar[4] = *(const float4*)&As[kk][ty * 8 + 4];
            *(float4*)&br[0] = *(const float4*)&Bs[kk][tx * 8];
            *(float4*)&br[4] = *(const float4*)&Bs[kk][tx * 8 + 4];
#pragma unroll
            for (int i = 0; i < 8; i++)
#pragma unroll
                for (int j = 0; j < 8; j++) acc[i][j] += ar[i] * br[j];
        }
    }

    // Epilogue: bias, optional relu, optional residual
#pragma unroll
    for (int i = 0; i < 8; i++) {
        const int r = row0 + ty * 8 + i;
#pragma unroll
        for (int j = 0; j < 8; j += 4) {
            const int c = col0 + tx * 8 + j;
            float4 o;
            o.x = acc[i][j + 0] + bias[c + 0];
            o.y = acc[i][j + 1] + bias[c + 1];
            o.z = acc[i][j + 2] + bias[c + 2];
            o.w = acc[i][j + 3] + bias[c + 3];
            if (relu) {
                o.x = fmaxf(o.x, 0.f); o.y = fmaxf(o.y, 0.f);
                o.z = fmaxf(o.z, 0.f); o.w = fmaxf(o.w, 0.f);
            }
            if (resid) {
                float4 rv = *(const float4*)(resid + (size_t)r * N + c);
                o.x += rv.x; o.y += rv.y; o.z += rv.z; o.w += rv.w;
            }
            *(float4*)(C + (size_t)r * N + c) = o;
        }
    }
}

// ---------------------------------------------------------------------------
// Causal flash attention.
// Q,K,V layout: [B, S, D] with head h at columns [h*64, h*64+64).
// Grid: (S/64, H, B). Block: 128 threads = 64 queries x 2 dim-halves (32 each).
// Online softmax, K/V tiles of 64 rows in smem.
// ---------------------------------------------------------------------------
__global__ __launch_bounds__(128) void attn_kernel(
    const float* __restrict__ Q, const float* __restrict__ K,
    const float* __restrict__ V, float* __restrict__ O)
{
    const int qb = blockIdx.x;     // query tile
    const int h  = blockIdx.y;
    const int b  = blockIdx.z;
    const int tid  = threadIdx.x;
    const int qi   = tid >> 1;     // 0..63 local query
    const int half = tid & 1;      // which 32-dim half
    const int d0   = half * 32;
    const int qrow = qb * 64 + qi; // global query index

    __shared__ float Ks[64][64];
    __shared__ float Vs[64][64];

    // Load this thread's half of its query row, pre-scaled by 1/sqrt(DK)
    float qreg[32];
    {
        const float sc = 0.125f;  // 1/sqrt(64)
        const float* qp = Q + ((size_t)b * SS + qrow) * DD + h * DKK + d0;
#pragma unroll
        for (int i = 0; i < 8; i++) {
            float4 t = *(const float4*)(qp + 4 * i);
            qreg[4*i+0] = t.x * sc; qreg[4*i+1] = t.y * sc;
            qreg[4*i+2] = t.z * sc; qreg[4*i+3] = t.w * sc;
        }
    }

    float acc[32];
#pragma unroll
    for (int d = 0; d < 32; d++) acc[d] = 0.f;
    float m = -1e30f, l = 0.f;

    const int ntiles = qb + 1;   // causal: key tiles 0..qb
    for (int kt = 0; kt < ntiles; kt++) {
        __syncthreads();
        // Load 64x64 K and V tiles (1024 float4 each; 8 per thread)
        const size_t base = ((size_t)b * SS + (size_t)kt * 64) * DD + h * DKK;
#pragma unroll
        for (int it = 0; it < 8; it++) {
            const int i = tid + it * 128;       // 0..1023
            const int row = i >> 4;
            const int c4  = (i & 15) * 4;
            *(float4*)&Ks[row][c4] = *(const float4*)(K + base + (size_t)row * DD + c4);
            *(float4*)&Vs[row][c4] = *(const float4*)(V + base + (size_t)row * DD + c4);
        }
        __syncthreads();

        // Scores for 64 keys (partial over this thread's 32 dims)
        float s[64];
#pragma unroll
        for (int j = 0; j < 64; j++) {
            const float4* kr = (const float4*)&Ks[j][d0];
            float p = 0.f;
#pragma unroll
            for (int i = 0; i < 8; i++) {
                float4 t = kr[i];
                p += qreg[4*i+0]*t.x + qreg[4*i+1]*t.y
                   + qreg[4*i+2]*t.z + qreg[4*i+3]*t.w;
            }
            s[j] = p;
        }
        // Combine the two dim-halves (partner lanes differ in bit 0)
#pragma unroll
        for (int j = 0; j < 64; j++)
            s[j] += __shfl_xor_sync(0xffffffffu, s[j], 1);

        // Causal mask on the diagonal tile
        if (kt == qb) {
#pragma unroll
            for (int j = 0; j < 64; j++)
                if (j > qi) s[j] = -1e30f;
        }

        // Online softmax update
        float mt = m;
#pragma unroll
        for (int j = 0; j < 64; j++) mt = fmaxf(mt, s[j]);
        const float alpha = __expf(m - mt);
        m = mt;
        l *= alpha;
#pragma unroll
        for (int d = 0; d < 32; d++) acc[d] *= alpha;

#pragma unroll
        for (int j = 0; j < 64; j++) {
            const float p = __expf(s[j] - m);
            l += p;
            const float4* vr = (const float4*)&Vs[j][d0];
#pragma unroll
            for (int i = 0; i < 8; i++) {
                float4 t = vr[i];
                acc[4*i+0] += p * t.x; acc[4*i+1] += p * t.y;
                acc[4*i+2] += p * t.z; acc[4*i+3] += p * t.w;
            }
        }
    }

    const float inv = 1.f / l;
    float* op = O + ((size_t)b * SS + qrow) * DD + h * DKK + d0;
#pragma unroll
    for (int i = 0; i < 8; i++) {
        float4 t;
        t.x = acc[4*i+0] * inv; t.y = acc[4*i+1] * inv;
        t.z = acc[4*i+2] * inv; t.w = acc[4*i+3] * inv;
        *(float4*)(op + 4 * i) = t;
    }
}

// ---------------------------------------------------------------------------
// LayerNorm over last dim (512). One block (128 threads) per row.
// ---------------------------------------------------------------------------
__device__ __forceinline__ float block_sum(float v) {
    __shared__ float red[4];
#pragma unroll
    for (int o = 16; o; o >>= 1) v += __shfl_xor_sync(0xffffffffu, v, o);
    const int lane = threadIdx.x & 31, wid = threadIdx.x >> 5;
    if (lane == 0) red[wid] = v;
    __syncthreads();
    float r = (red[0] + red[1]) + (red[2] + red[3]);
    __syncthreads();
    return r;
}

__global__ __launch_bounds__(128) void ln_kernel(
    const float* __restrict__ X, const float* __restrict__ g,
    const float* __restrict__ be, float* __restrict__ out)
{
    const int row = blockIdx.x;
    const int tid = threadIdx.x;
    const float4 v = ((const float4*)(X + (size_t)row * DD))[tid];

    float s = block_sum(v.x + v.y + v.z + v.w);
    const float mu = s * (1.f / DD);
    const float dx = v.x - mu, dy = v.y - mu, dz = v.z - mu, dw = v.w - mu;
    float sq = block_sum(dx*dx + dy*dy + dz*dz + dw*dw);
    const float rstd = rsqrtf(sq * (1.f / DD) + 1e-5f);

    const float4 gv  = ((const float4*)g)[tid];
    const float4 bv  = ((const float4*)be)[tid];
    float4 o;
    o.x = dx * rstd * gv.x + bv.x;
    o.y = dy * rstd * gv.y + bv.y;
    o.z = dz * rstd * gv.z + bv.z;
    o.w = dw * rstd * gv.w + bv.w;
    ((float4*)(out + (size_t)row * DD))[tid] = o;
}

// ---------------------------------------------------------------------------
// Launch
// ---------------------------------------------------------------------------
static void run_sgemm(const float* A, const float* B, const float* bias,
                      const float* resid, float* C, int M, int N, int K, int relu)
{
    dim3 grid(N / 128, M / 128), block(256);
    sgemm_kernel<<<grid, block>>>(A, B, bias, resid, C, M, N, K, relu);
}

extern "C" void kernel_launch(void* const* d_in, const int* in_sizes, int n_in,
                              void* d_out, int out_size)
{
    (void)in_sizes; (void)n_in; (void)out_size;
    const float* x   = (const float*)d_in[0];
    // d_in[1] = mask (deterministic causal tril) — applied analytically
    const float* wq  = (const float*)d_in[2];
    const float* bq  = (const float*)d_in[3];
    const float* wk  = (const float*)d_in[4];
    const float* bk  = (const float*)d_in[5];
    const float* wv  = (const float*)d_in[6];
    const float* bv  = (const float*)d_in[7];
    const float* wo  = (const float*)d_in[8];
    const float* bo  = (const float*)d_in[9];
    const float* w1  = (const float*)d_in[10];
    const float* b1  = (const float*)d_in[11];
    const float* w2  = (const float*)d_in[12];
    const float* b2  = (const float*)d_in[13];
    const float* g1  = (const float*)d_in[14];
    const float* be1 = (const float*)d_in[15];
    const float* g2  = (const float*)d_in[16];
    const float* be2 = (const float*)d_in[17];
    float* out = (float*)d_out;

    float *q, *k, *v, *ctx, *h, *ffn;
    cudaGetSymbolAddress((void**)&q,   g_q);
    cudaGetSymbolAddress((void**)&k,   g_k);
    cudaGetSymbolAddress((void**)&v,   g_v);
    cudaGetSymbolAddress((void**)&ctx, g_ctx);
    cudaGetSymbolAddress((void**)&h,   g_h);
    cudaGetSymbolAddress((void**)&ffn, g_ffn);

    // QKV projections
    run_sgemm(x, wq, bq, nullptr, q, MM, DD, DD, 0);
    run_sgemm(x, wk, bk, nullptr, k, MM, DD, DD, 0);
    run_sgemm(x, wv, bv, nullptr, v, MM, DD, DD, 0);

    // Causal attention -> ctx [B,S,D]
    attn_kernel<<<dim3(SS / 64, HH, BB), 128>>>(q, k, v, ctx);

    // Output projection + residual (x) -> reuse q as pre-LN buffer
    run_sgemm(ctx, wo, bo, x, q, MM, DD, DD, 0);
    ln_kernel<<<MM, 128>>>(q, g1, be1, h);

    // FFN
    run_sgemm(h,   w1, b1, nullptr, ffn, MM, FFF, DD, 1);
    run_sgemm(ffn, w2, b2, h,       q,   MM, DD, FFF, 0);
    ln_kernel<<<MM, 128>>>(q, g2, be2, out);
}

// round 3
// speedup vs baseline: 1.1382x; 1.1382x over previous
#include <cuda_runtime.h>
#include <cstdint>
#include <math.h>

// Problem constants
#define BB 4
#define SS 2048
#define DD 512
#define HH 8
#define DKK 64
#define FFF 2048
#define MM (BB * SS)   // 8192 rows

// ---------------------------------------------------------------------------
// Scratch (device globals — no allocation allowed)
// ---------------------------------------------------------------------------
__device__ float g_q  [MM * DD];
__device__ float g_k  [MM * DD];
__device__ float g_v  [MM * DD];
__device__ float g_ctx[MM * DD];
__device__ float g_h  [MM * DD];
__device__ float g_ffn[MM * FFF];

// ---------------------------------------------------------------------------
// Helpers
// ---------------------------------------------------------------------------
__device__ __forceinline__ float to_tf32(float x) {
    float r; asm("cvt.rna.tf32.f32 %0, %1;" : "=f"(r) : "f"(x)); return r;
}

__device__ __forceinline__ void mma_tf32(float c[4], const uint32_t a[4], const uint32_t b[2]) {
    asm volatile(
        "mma.sync.aligned.m16n8k8.row.col.f32.tf32.tf32.f32 "
        "{%0,%1,%2,%3}, {%4,%5,%6,%7}, {%8,%9}, {%0,%1,%2,%3};"
        : "+f"(c[0]), "+f"(c[1]), "+f"(c[2]), "+f"(c[3])
        : "r"(a[0]), "r"(a[1]), "r"(a[2]), "r"(a[3]), "r"(b[0]), "r"(b[1]));
}

#define SK 136   // smem row stride in floats (conflict-free for frag LDS + STS)

// A fragment (m16k8): a0 row=lane>>2 col=lane&3; a1 row+8; a2 col+4; a3 row+8,col+4
__device__ __forceinline__ void load_afrag(uint32_t a[4], const float* base,
                                           int krow, int mrow, int lane) {
    const float* p = base + (krow + (lane & 3)) * SK + mrow + (lane >> 2);
    a[0] = __float_as_uint(p[0]);
    a[1] = __float_as_uint(p[8]);
    a[2] = __float_as_uint(p[4 * SK]);
    a[3] = __float_as_uint(p[4 * SK + 8]);
}
// B fragment (k8n8): b0 row(k)=lane&3 col(n)=lane>>2; b1 k+4
__device__ __forceinline__ void load_bfrag(uint32_t b[2], const float* base,
                                           int krow, int ncol, int lane) {
    const float* p = base + (krow + (lane & 3)) * SK + ncol + (lane >> 2);
    b[0] = __float_as_uint(p[0]);
    b[1] = __float_as_uint(p[4 * SK]);
}

// ---------------------------------------------------------------------------
// tf32x3 HMMA GEMM: C[M,N] = A[M,K] @ B[K,N] + bias (+resid) (opt relu)
// CTA tile 128x128, BK=16, 256 threads (8 warps as 2m x 4n of 64x32 tiles).
// Double-buffered smem; hi/lo tf32 split stored as fp32.
// ---------------------------------------------------------------------------
#define TILE_F (16 * SK)                 // floats per array per stage (2176)
#define SMEM_BYTES (8 * TILE_F * 4)      // 4 arrays x 2 stages = 69632 B

__global__ __launch_bounds__(256, 2) void tc_gemm(
    const float* __restrict__ A, const float* __restrict__ Bw,
    const float* __restrict__ bias, const float* __restrict__ resid,
    float* __restrict__ C, int N, int K, int relu)
{
    extern __shared__ float sm[];
    const int tid  = threadIdx.x;
    const int lane = tid & 31;
    const int wid  = tid >> 5;
    const int m0 = blockIdx.y * 128, n0 = blockIdx.x * 128;
    const int wm = (wid & 1) * 64;       // warp m offset
    const int wn = (wid >> 1) * 32;      // warp n offset

    // gmem staging pattern
    const int am  = tid & 127;           // A row within tile
    const int akq = tid >> 7;            // A k-quad base (0/1)
    const int bn4 = (tid & 31) * 4;      // B col (float4)
    const int bk  = tid >> 5;            // B k row (0..7), +8 for it=1

    float cfr[4][4][4];
#pragma unroll
    for (int t = 0; t < 4; t++)
#pragma unroll
        for (int u = 0; u < 4; u++)
#pragma unroll
            for (int e = 0; e < 4; e++) cfr[t][u][e] = 0.f;

    float4 aR[2], bR[2];

    const int nst = K >> 4;              // BK = 16

    // ---- stage 0 load + store ----
#pragma unroll
    for (int it = 0; it < 2; it++) {
        aR[it] = *(const float4*)(A + (size_t)(m0 + am) * K + (akq + 2 * it) * 4);
        bR[it] = *(const float4*)(Bw + (size_t)(bk + it * 8) * N + n0 + bn4);
    }
    {
        float* AH = sm;            float* AL = sm + TILE_F;
        float* BH = sm + 2*TILE_F; float* BL = sm + 3*TILE_F;
#pragma unroll
        for (int it = 0; it < 2; it++) {
            const int k4 = (akq + 2 * it) * 4;
            const float av[4] = { aR[it].x, aR[it].y, aR[it].z, aR[it].w };
#pragma unroll
            for (int j = 0; j < 4; j++) {
                const float h = to_tf32(av[j]);
                AH[(k4 + j) * SK + am] = h;
                AL[(k4 + j) * SK + am] = to_tf32(av[j] - h);
            }
            const int kb = bk + it * 8;
            float4 h4, l4;
            h4.x = to_tf32(bR[it].x); l4.x = to_tf32(bR[it].x - h4.x);
            h4.y = to_tf32(bR[it].y); l4.y = to_tf32(bR[it].y - h4.y);
            h4.z = to_tf32(bR[it].z); l4.z = to_tf32(bR[it].z - h4.z);
            h4.w = to_tf32(bR[it].w); l4.w = to_tf32(bR[it].w - h4.w);
            *(float4*)(BH + kb * SK + bn4) = h4;
            *(float4*)(BL + kb * SK + bn4) = l4;
        }
    }
    __syncthreads();

    for (int i = 0; i < nst; i++) {
        // prefetch next stage into regs
        if (i + 1 < nst) {
            const int k0 = (i + 1) << 4;
#pragma unroll
            for (int it = 0; it < 2; it++) {
                aR[it] = *(const float4*)(A + (size_t)(m0 + am) * K + k0 + (akq + 2 * it) * 4);
                bR[it] = *(const float4*)(Bw + (size_t)(k0 + bk + it * 8) * N + n0 + bn4);
            }
        }

        // compute current stage (2 k-steps of 8)
        {
            const float* AH = sm + (size_t)(i & 1) * 4 * TILE_F;
            const float* AL = AH + TILE_F;
            const float* BH = AH + 2 * TILE_F;
            const float* BL = AH + 3 * TILE_F;
#pragma unroll
            for (int ks = 0; ks < 2; ks++) {
                const int krow = ks * 8;
                uint32_t af[4][4], bf[4][2];
                // hi x hi
#pragma unroll
                for (int t = 0; t < 4; t++) load_afrag(af[t], AH, krow, wm + t * 16, lane);
#pragma unroll
                for (int u = 0; u < 4; u++) load_bfrag(bf[u], BH, krow, wn + u * 8, lane);
#pragma unroll
                for (int t = 0; t < 4; t++)
#pragma unroll
                    for (int u = 0; u < 4; u++) mma_tf32(cfr[t][u], af[t], bf[u]);
                // hi x lo (reuse A hi)
#pragma unroll
                for (int u = 0; u < 4; u++) load_bfrag(bf[u], BL, krow, wn + u * 8, lane);
#pragma unroll
                for (int t = 0; t < 4; t++)
#pragma unroll
                    for (int u = 0; u < 4; u++) mma_tf32(cfr[t][u], af[t], bf[u]);
                // lo x hi
#pragma unroll
                for (int t = 0; t < 4; t++) load_afrag(af[t], AL, krow, wm + t * 16, lane);
#pragma unroll
                for (int u = 0; u < 4; u++) load_bfrag(bf[u], BH, krow, wn + u * 8, lane);
#pragma unroll
                for (int t = 0; t < 4; t++)
#pragma unroll
                    for (int u = 0; u < 4; u++) mma_tf32(cfr[t][u], af[t], bf[u]);
            }
        }

        // store next stage to the other buffer
        if (i + 1 < nst) {
            float* AH = sm + (size_t)((i + 1) & 1) * 4 * TILE_F;
            float* AL = AH + TILE_F;
            float* BH = AH + 2 * TILE_F;
            float* BL = AH + 3 * TILE_F;
#pragma unroll
            for (int it = 0; it < 2; it++) {
                const int k4 = (akq + 2 * it) * 4;
                const float av[4] = { aR[it].x, aR[it].y, aR[it].z, aR[it].w };
#pragma unroll
                for (int j = 0; j < 4; j++) {
                    const float h = to_tf32(av[j]);
                    AH[(k4 + j) * SK + am] = h;
                    AL[(k4 + j) * SK + am] = to_tf32(av[j] - h);
                }
                const int kb = bk + it * 8;
                float4 h4, l4;
                h4.x = to_tf32(bR[it].x); l4.x = to_tf32(bR[it].x - h4.x);
                h4.y = to_tf32(bR[it].y); l4.y = to_tf32(bR[it].y - h4.y);
                h4.z = to_tf32(bR[it].z); l4.z = to_tf32(bR[it].z - h4.z);
                h4.w = to_tf32(bR[it].w); l4.w = to_tf32(bR[it].w - h4.w);
                *(float4*)(BH + kb * SK + bn4) = h4;
                *(float4*)(BL + kb * SK + bn4) = l4;
            }
        }
        __syncthreads();
    }

    // ---- epilogue: bias (+relu) (+resid), write C ----
#pragma unroll
    for (int t = 0; t < 4; t++) {
        const int r0 = m0 + wm + t * 16 + (lane >> 2);
        const int r1 = r0 + 8;
#pragma unroll
        for (int u = 0; u < 4; u++) {
            const int c = n0 + wn + u * 8 + 2 * (lane & 3);
            const float2 b2 = *(const float2*)(bias + c);
            float o0 = cfr[t][u][0] + b2.x, o1 = cfr[t][u][1] + b2.y;
            float o2 = cfr[t][u][2] + b2.x, o3 = cfr[t][u][3] + b2.y;
            if (relu) {
                o0 = fmaxf(o0, 0.f); o1 = fmaxf(o1, 0.f);
                o2 = fmaxf(o2, 0.f); o3 = fmaxf(o3, 0.f);
            }
            if (resid) {
                const float2 ra = *(const float2*)(resid + (size_t)r0 * N + c);
                const float2 rb = *(const float2*)(resid + (size_t)r1 * N + c);
                o0 += ra.x; o1 += ra.y; o2 += rb.x; o3 += rb.y;
            }
            *(float2*)(C + (size_t)r0 * N + c) = make_float2(o0, o1);
            *(float2*)(C + (size_t)r1 * N + c) = make_float2(o2, o3);
        }
    }
}

// ---------------------------------------------------------------------------
// Causal flash attention (unchanged).
// ---------------------------------------------------------------------------
__global__ __launch_bounds__(128) void attn_kernel(
    const float* __restrict__ Q, const float* __restrict__ K,
    const float* __restrict__ V, float* __restrict__ O)
{
    const int qb = blockIdx.x;
    const int h  = blockIdx.y;
    const int b  = blockIdx.z;
    const int tid  = threadIdx.x;
    const int qi   = tid >> 1;
    const int half = tid & 1;
    const int d0   = half * 32;
    const int qrow = qb * 64 + qi;

    __shared__ float Ks[64][64];
    __shared__ float Vs[64][64];

    float qreg[32];
    {
        const float sc = 0.125f;
        const float* qp = Q + ((size_t)b * SS + qrow) * DD + h * DKK + d0;
#pragma unroll
        for (int i = 0; i < 8; i++) {
            float4 t = *(const float4*)(qp + 4 * i);
            qreg[4*i+0] = t.x * sc; qreg[4*i+1] = t.y * sc;
            qreg[4*i+2] = t.z * sc; qreg[4*i+3] = t.w * sc;
        }
    }

    float acc[32];
#pragma unroll
    for (int d = 0; d < 32; d++) acc[d] = 0.f;
    float m = -1e30f, l = 0.f;

    const int ntiles = qb + 1;
    for (int kt = 0; kt < ntiles; kt++) {
        __syncthreads();
        const size_t base = ((size_t)b * SS + (size_t)kt * 64) * DD + h * DKK;
#pragma unroll
        for (int it = 0; it < 8; it++) {
            const int i = tid + it * 128;
            const int row = i >> 4;
            const int c4  = (i & 15) * 4;
            *(float4*)&Ks[row][c4] = *(const float4*)(K + base + (size_t)row * DD + c4);
            *(float4*)&Vs[row][c4] = *(const float4*)(V + base + (size_t)row * DD + c4);
        }
        __syncthreads();

        float s[64];
#pragma unroll
        for (int j = 0; j < 64; j++) {
            const float4* kr = (const float4*)&Ks[j][d0];
            float p = 0.f;
#pragma unroll
            for (int i = 0; i < 8; i++) {
                float4 t = kr[i];
                p += qreg[4*i+0]*t.x + qreg[4*i+1]*t.y
                   + qreg[4*i+2]*t.z + qreg[4*i+3]*t.w;
            }
            s[j] = p;
        }
#pragma unroll
        for (int j = 0; j < 64; j++)
            s[j] += __shfl_xor_sync(0xffffffffu, s[j], 1);

        if (kt == qb) {
#pragma unroll
            for (int j = 0; j < 64; j++)
                if (j > qi) s[j] = -1e30f;
        }

        float mt = m;
#pragma unroll
        for (int j = 0; j < 64; j++) mt = fmaxf(mt, s[j]);
        const float alpha = __expf(m - mt);
        m = mt;
        l *= alpha;
#pragma unroll
        for (int d = 0; d < 32; d++) acc[d] *= alpha;

#pragma unroll
        for (int j = 0; j < 64; j++) {
            const float p = __expf(s[j] - m);
            l += p;
            const float4* vr = (const float4*)&Vs[j][d0];
#pragma unroll
            for (int i = 0; i < 8; i++) {
                float4 t = vr[i];
                acc[4*i+0] += p * t.x; acc[4*i+1] += p * t.y;
                acc[4*i+2] += p * t.z; acc[4*i+3] += p * t.w;
            }
        }
    }

    const float inv = 1.f / l;
    float* op = O + ((size_t)b * SS + qrow) * DD + h * DKK + d0;
#pragma unroll
    for (int i = 0; i < 8; i++) {
        float4 t;
        t.x = acc[4*i+0] * inv; t.y = acc[4*i+1] * inv;
        t.z = acc[4*i+2] * inv; t.w = acc[4*i+3] * inv;
        *(float4*)(op + 4 * i) = t;
    }
}

// ---------------------------------------------------------------------------
// LayerNorm over last dim (512). One block (128 threads) per row.
// ---------------------------------------------------------------------------
__device__ __forceinline__ float block_sum(float v) {
    __shared__ float red[4];
#pragma unroll
    for (int o = 16; o; o >>= 1) v += __shfl_xor_sync(0xffffffffu, v, o);
    const int lane = threadIdx.x & 31, wid = threadIdx.x >> 5;
    if (lane == 0) red[wid] = v;
    __syncthreads();
    float r = (red[0] + red[1]) + (red[2] + red[3]);
    __syncthreads();
    return r;
}

__global__ __launch_bounds__(128) void ln_kernel(
    const float* __restrict__ X, const float* __restrict__ g,
    const float* __restrict__ be, float* __restrict__ out)
{
    const int row = blockIdx.x;
    const int tid = threadIdx.x;
    const float4 v = ((const float4*)(X + (size_t)row * DD))[tid];

    float s = block_sum(v.x + v.y + v.z + v.w);
    const float mu = s * (1.f / DD);
    const float dx = v.x - mu, dy = v.y - mu, dz = v.z - mu, dw = v.w - mu;
    float sq = block_sum(dx*dx + dy*dy + dz*dz + dw*dw);
    const float rstd = rsqrtf(sq * (1.f / DD) + 1e-5f);

    const float4 gv  = ((const float4*)g)[tid];
    const float4 bv  = ((const float4*)be)[tid];
    float4 o;
    o.x = dx * rstd * gv.x + bv.x;
    o.y = dy * rstd * gv.y + bv.y;
    o.z = dz * rstd * gv.z + bv.z;
    o.w = dw * rstd * gv.w + bv.w;
    ((float4*)(out + (size_t)row * DD))[tid] = o;
}

// ---------------------------------------------------------------------------
// Launch
// ---------------------------------------------------------------------------
static void run_tc_gemm(const float* A, const float* B, const float* bias,
                        const float* resid, float* C, int M, int N, int K, int relu)
{
    dim3 grid(N / 128, M / 128), block(256);
    tc_gemm<<<grid, block, SMEM_BYTES>>>(A, B, bias, resid, C, N, K, relu);
}

extern "C" void kernel_launch(void* const* d_in, const int* in_sizes, int n_in,
                              void* d_out, int out_size)
{
    (void)in_sizes; (void)n_in; (void)out_size;
    const float* x   = (const float*)d_in[0];
    // d_in[1] = mask (deterministic causal tril) — applied analytically
    const float* wq  = (const float*)d_in[2];
    const float* bq  = (const float*)d_in[3];
    const float* wk  = (const float*)d_in[4];
    const float* bk  = (const float*)d_in[5];
    const float* wv  = (const float*)d_in[6];
    const float* bv  = (const float*)d_in[7];
    const float* wo  = (const float*)d_in[8];
    const float* bo  = (const float*)d_in[9];
    const float* w1  = (const float*)d_in[10];
    const float* b1  = (const float*)d_in[11];
    const float* w2  = (const float*)d_in[12];
    const float* b2  = (const float*)d_in[13];
    const float* g1  = (const float*)d_in[14];
    const float* be1 = (const float*)d_in[15];
    const float* g2  = (const float*)d_in[16];
    const float* be2 = (const float*)d_in[17];
    float* out = (float*)d_out;

    float *q, *k, *v, *ctx, *h, *ffn;
    cudaGetSymbolAddress((void**)&q,   g_q);
    cudaGetSymbolAddress((void**)&k,   g_k);
    cudaGetSymbolAddress((void**)&v,   g_v);
    cudaGetSymbolAddress((void**)&ctx, g_ctx);
    cudaGetSymbolAddress((void**)&h,   g_h);
    cudaGetSymbolAddress((void**)&ffn, g_ffn);

    cudaFuncSetAttribute(tc_gemm, cudaFuncAttributeMaxDynamicSharedMemorySize, SMEM_BYTES);

    // QKV projections (HMMA tf32x3)
    run_tc_gemm(x, wq, bq, nullptr, q, MM, DD, DD, 0);
    run_tc_gemm(x, wk, bk, nullptr, k, MM, DD, DD, 0);
    run_tc_gemm(x, wv, bv, nullptr, v, MM, DD, DD, 0);

    // Causal attention -> ctx [B,S,D]
    attn_kernel<<<dim3(SS / 64, HH, BB), 128>>>(q, k, v, ctx);

    // Output projection + residual (x) -> reuse q as pre-LN buffer
    run_tc_gemm(ctx, wo, bo, x, q, MM, DD, DD, 0);
    ln_kernel<<<MM, 128>>>(q, g1, be1, h);

    // FFN
    run_tc_gemm(h,   w1, b1, nullptr, ffn, MM, FFF, DD, 1);
    run_tc_gemm(ffn, w2, b2, h,       q,   MM, DD, FFF, 0);
    ln_kernel<<<MM, 128>>>(q, g2, be2, out);
}